// round 12
// baseline (speedup 1.0000x reference)
#include <cuda_runtime.h>
#include <cuda_fp16.h>
#include <cstdint>

#define Tn 8192
#define Hn 1024
#define In 2816
#define En 8
#define MAXP 17408  // 16384 pairs + per-expert 128-alignment padding

// ------------------- device scratch (no allocations allowed) -----------------
__device__ int    g_cnt[En];
__device__ int    g_cur[En];
__device__ int    g_off[En + 1];
__device__ int    g_eid[Tn * 2];
__device__ float  g_ew[Tn * 2];
__device__ int    g_tok[MAXP];
__device__ float  g_wt[MAXP];
__device__ __half g_xh[(size_t)MAXP * Hn];           // gathered x rows, fp16
__device__ __half g_hbh[(size_t)MAXP * In];          // silu(gate)*up, fp16
__device__ __half g_w13h[(size_t)En * 2 * In * Hn];  // fp16 w13 (92MB)
__device__ __half g_w2h[(size_t)En * Hn * In];       // fp16 w2  (46MB)

static constexpr long N1_4  = (long)En * 2 * In * Hn / 4;  // w13 float4 count
static constexpr long N1_4H = N1_4 / 2;                    // split point
static constexpr long N2_4  = (long)En * Hn * In / 4;      // w2 float4 count

// ------------------- helpers -------------------------------------------------
__device__ __forceinline__ uint32_t smem_u32(const void* p) {
    uint32_t a;
    asm("{ .reg .u64 t; cvta.to.shared.u64 t, %1; cvt.u32.u64 %0, t; }" : "=r"(a) : "l"(p));
    return a;
}
__device__ __forceinline__ void cp16(uint32_t saddr, const void* gsrc) {
    asm volatile("cp.async.cg.shared.global [%0], [%1], 16;\n" :: "r"(saddr), "l"(gsrc));
}
// fp16 m16n8k16 mma, fp32 accumulate
__device__ __forceinline__ void mma16(float* c, const uint32_t* a, const uint32_t* b) {
    asm volatile(
        "mma.sync.aligned.m16n8k16.row.col.f32.f16.f16.f32 "
        "{%0,%1,%2,%3}, {%4,%5,%6,%7}, {%8,%9}, {%0,%1,%2,%3};\n"
        : "+f"(c[0]), "+f"(c[1]), "+f"(c[2]), "+f"(c[3])
        : "r"(a[0]), "r"(a[1]), "r"(a[2]), "r"(a[3]), "r"(b[0]), "r"(b[1]));
}
__device__ __forceinline__ void ldm4(uint32_t* r, uint32_t addr) {
    asm volatile("ldmatrix.sync.aligned.m8n8.x4.shared.b16 {%0,%1,%2,%3}, [%4];"
                 : "=r"(r[0]), "=r"(r[1]), "=r"(r[2]), "=r"(r[3]) : "r"(addr));
}
__device__ __forceinline__ uint32_t h2u(__half2 h) { return *(uint32_t*)&h; }

__device__ __forceinline__ void cvt4(const float* src4, __half* dst4, long i) {
    float4 v = ((const float4*)src4)[i];
    uint2 pk;
    pk.x = h2u(__floats2half2_rn(v.x, v.y));
    pk.y = h2u(__floats2half2_rn(v.z, v.w));
    ((uint2*)dst4)[i] = pk;
}

// smem layout: K-chunk = 128 halves (256 B/row), pitch 136 halves (272 B/row).
// Stage: A 128x272B = 34,816 B; B 256x272B = 69,632 B -> 104,448 B.
static constexpr int ROWP_B = 272;              // row pitch bytes
static constexpr int STG_B  = 104448;           // bytes per stage
static constexpr int BOFF_B = 34816;            // B offset within stage
static constexpr int SMEM_BYTES = STG_B * 2;    // 208,896 B (2 stages)

// ------------------- kernel: reset per-call state -----------------------------
__global__ void k_init() {
    int i = blockIdx.x * blockDim.x + threadIdx.x;
    if (i < En) { g_cnt[i] = 0; g_cur[i] = 0; }
    for (int s = i; s < MAXP; s += gridDim.x * blockDim.x) {
        g_tok[s] = -1;
        g_wt[s] = 0.0f;
    }
}

// ------------------- kernel: router ------------------------------------------
__global__ void k_router(const float* __restrict__ logits) {
    int t = blockIdx.x * blockDim.x + threadIdx.x;
    if (t >= Tn) return;
    float v[En];
#pragma unroll
    for (int e = 0; e < En; e++) v[e] = logits[t * En + e];
    int b0 = 0; float m0 = v[0];
#pragma unroll
    for (int e = 1; e < En; e++) if (v[e] > m0) { m0 = v[e]; b0 = e; }
    int b1 = -1; float m1 = -3.0e38f;
#pragma unroll
    for (int e = 0; e < En; e++) if (e != b0 && v[e] > m1) { m1 = v[e]; b1 = e; }
    float e1 = expf(m1 - m0);
    float inv = 1.0f / (1.0f + e1);
    g_eid[2 * t] = b0;     g_ew[2 * t] = inv;
    g_eid[2 * t + 1] = b1; g_ew[2 * t + 1] = e1 * inv;
    atomicAdd(&g_cnt[b0], 1);
    atomicAdd(&g_cnt[b1], 1);
}

// ------------------- kernel: 128-aligned offsets ------------------------------
__global__ void k_off() {
    if (threadIdx.x == 0 && blockIdx.x == 0) {
        int o = 0;
        g_off[0] = 0;
        for (int e = 0; e < En; e++) {
            o += (g_cnt[e] + 127) & ~127;
            g_off[e + 1] = o;
        }
    }
}

// ------------------- kernel: scatter + w13 cvt (part 1) -----------------------
__global__ void k_scatter(const float* __restrict__ w13) {
    long gid = (long)blockIdx.x * blockDim.x + threadIdx.x;
    if (gid < Tn) {
        int t = (int)gid;
#pragma unroll
        for (int k = 0; k < 2; k++) {
            int e = g_eid[2 * t + k];
            int pos = atomicAdd(&g_cur[e], 1);
            int s = g_off[e] + pos;
            g_tok[s] = t;
            g_wt[s] = g_ew[2 * t + k];
        }
    }
    const long stride = (long)gridDim.x * blockDim.x;
    for (long i = gid; i < N1_4H; i += stride) cvt4(w13, g_w13h, i);
}

// ------------------- kernel: gather + w13 cvt (part 2) + zero out -------------
__global__ void k_gather(const float* __restrict__ x, const float* __restrict__ w13,
                         float* __restrict__ out) {
    int s = blockIdx.x;
    int tok = g_tok[s];
    uint2 pk = { 0u, 0u };
    if (tok >= 0) {
        float4 v = *(const float4*)&x[(size_t)tok * Hn + threadIdx.x * 4];
        pk.x = h2u(__floats2half2_rn(v.x, v.y));
        pk.y = h2u(__floats2half2_rn(v.z, v.w));
    }
    *(uint2*)&g_xh[(size_t)s * Hn + threadIdx.x * 4] = pk;

    const long idx = (long)blockIdx.x * blockDim.x + threadIdx.x;
    // zero the output accumulator (GEMM2 atomically adds into it)
    if (idx < (long)Tn * Hn / 4)
        ((float4*)out)[idx] = make_float4(0.f, 0.f, 0.f, 0.f);
    // w13 conversion, second half
    const long stride = (long)gridDim.x * blockDim.x;
    for (long i = N1_4H + idx; i < N1_4; i += stride) cvt4(w13, g_w13h, i);
}

// w2 conversion slice, executed inside k_gemm1 by every CTA
__device__ __forceinline__ void cvt_w2_slice(const float* __restrict__ w2,
                                             long ctaid, long ncta, int tid) {
    const long stride = ncta * 256;
    for (long i = ctaid * 256 + tid; i < N2_4; i += stride) cvt4(w2, g_w2h, i);
}

// =============================================================================
// GEMM mainloop: CTA tile M=128 x 256 B-rows, fp16 m16n8k16.
// K-chunk = 128 halves (256 B/row), pitch-136 smem rows, 2-stage cp.async
// pipeline (lookahead 1), ldmatrix fragment loads, 8 warps of 64x64.
// =============================================================================

__device__ __forceinline__ int ldm_lane_off(int lane) {
    int lr = lane & 7, grp = lane >> 3;
    int rowoff = lr + (grp & 1) * 8;
    int coloff = (grp >> 1) * 8;
    return rowoff * ROWP_B + coloff * 2;
}

#define LOAD_CHUNK(c, st) do {                                                     \
    const uint32_t _sA = sA0 + (st) * STG_B;                                       \
    const uint32_t _sB = sB0 + (st) * STG_B;                                       \
    _Pragma("unroll")                                                              \
    for (int q = 0; q < 8; q++)                                                    \
        cp16(_sA + q * 16 * ROWP_B, pA0 + (size_t)q * 16 * strA + (c) * 128);      \
    _Pragma("unroll")                                                              \
    for (int q = 0; q < 16; q++)                                                   \
        cp16(_sB + q * 16 * ROWP_B, B_ADDR(q) + (c) * 128);                        \
    asm volatile("cp.async.commit_group;" ::: "memory");                           \
} while (0)

#define GEMM_MAINLOOP(NC)                                                          \
    LOAD_CHUNK(0, 0);                                                              \
    LOAD_CHUNK(1, 1);                                                              \
    for (int i = 0; i < (NC); i++) {                                               \
        const int st = i & 1;                                                      \
        asm volatile("cp.async.wait_group 1;" ::: "memory");                       \
        __syncthreads();                                                           \
        const uint32_t aS = sbA + st * STG_B;                                      \
        const uint32_t bS = sbB + st * STG_B;                                      \
        _Pragma("unroll")                                                          \
        for (int ks = 0; ks < 8; ks++) {                                           \
            const int k0b = ks * 32;                                               \
            uint32_t af[4][4], bf[8][2];                                           \
            _Pragma("unroll")                                                      \
            for (int mi = 0; mi < 4; mi++)                                         \
                ldm4(af[mi], aS + (mBase + mi * 16) * ROWP_B + k0b + loff);        \
            _Pragma("unroll")                                                      \
            for (int nj = 0; nj < 4; nj++) {                                       \
                uint32_t t4[4];                                                    \
                ldm4(t4, bS + (nBase + nj * 16) * ROWP_B + k0b + loff);            \
                bf[nj * 2][0] = t4[0]; bf[nj * 2 + 1][0] = t4[1];                  \
                bf[nj * 2][1] = t4[2]; bf[nj * 2 + 1][1] = t4[3];                  \
            }                                                                      \
            _Pragma("unroll")                                                      \
            for (int mi = 0; mi < 4; mi++)                                         \
                _Pragma("unroll")                                                  \
                for (int ni = 0; ni < 8; ni++) mma16(acc[mi][ni], af[mi], bf[ni]); \
        }                                                                          \
        __syncthreads();                                                           \
        if (i + 2 < (NC)) LOAD_CHUNK(i + 2, st);                                   \
        else asm volatile("cp.async.commit_group;" ::: "memory");                  \
    }

// =============================================================================
// GEMM1: h = silu(x W1^T) * (x W3^T). B-rows 0..127 = gate, 128..255 = up.
// Also converts a slice of w2 to fp16 per CTA (overlapped with the wave).
// =============================================================================
__global__ __launch_bounds__(256, 1) void k_gemm1(const float* __restrict__ w2) {
    extern __shared__ __align__(16) char smraw[];
    const int mtile = blockIdx.x, ntile = blockIdx.y;  // mtile fast (A L2-reuse)
    const int tid = threadIdx.x;
    const long ctaid = (long)blockIdx.y * gridDim.x + blockIdx.x;
    const long ncta = (long)gridDim.x * gridDim.y;

    if (mtile * 128 >= g_off[En]) {
        cvt_w2_slice(w2, ctaid, ncta, tid);
        return;
    }
    int e = 0;
#pragma unroll
    for (int i = 0; i < En; i++) if (mtile * 128 >= g_off[i + 1]) e = i + 1;
    const int n0 = ntile * 128;

    const uint32_t sb = smem_u32(smraw);
    const uint32_t sbA = sb, sbB = sb + BOFF_B;

    // loader bases: r0 = tid>>4 (0..15), sg = tid&15
    const int r0 = tid >> 4, sg = tid & 15;
    const int strA = Hn;  // halves per A row
    const __half* pA0 = g_xh + (size_t)(mtile * 128 + r0) * Hn + sg * 8;
    const __half* pBg = g_w13h + ((size_t)e * 2 * In + n0 + r0) * Hn + sg * 8;
    const __half* pBu = g_w13h + ((size_t)e * 2 * In + In + n0 + r0) * Hn + sg * 8;
    const uint32_t sA0 = sbA + r0 * ROWP_B + sg * 16;
    const uint32_t sB0 = sbB + r0 * ROWP_B + sg * 16;
#define B_ADDR(q) ((q) < 8 ? (pBg + (size_t)(q) * 16 * Hn) : (pBu + (size_t)((q) - 8) * 16 * Hn))

    const int w = tid >> 5, lane = tid & 31;
    const int mBase = (w & 1) * 64, nBase = (w >> 1) * 64;
    const int qr = lane >> 2, qc = lane & 3;
    const int loff = ldm_lane_off(lane);

    float acc[4][8][4];
#pragma unroll
    for (int a = 0; a < 4; a++)
#pragma unroll
        for (int b = 0; b < 8; b++)
#pragma unroll
            for (int c = 0; c < 4; c++) acc[a][b][c] = 0.0f;

    GEMM_MAINLOOP(Hn / 128)  // 8 chunks
#undef B_ADDR

    // ---- epilogue: gate warps stage to smem; up warps compute silu(g)*u ------
    float* sE = (float*)smraw;  // 128 x pitch-130 floats = 66,560 B (fits)
    if (nBase < 128) {
#pragma unroll
        for (int mi = 0; mi < 4; mi++)
#pragma unroll
            for (int ni = 0; ni < 8; ni++) {
                int r = mBase + mi * 16 + qr;
                int c = nBase + ni * 8 + qc * 2;
                sE[r * 130 + c] = acc[mi][ni][0];
                sE[r * 130 + c + 1] = acc[mi][ni][1];
                sE[(r + 8) * 130 + c] = acc[mi][ni][2];
                sE[(r + 8) * 130 + c + 1] = acc[mi][ni][3];
            }
    }
    __syncthreads();
    if (nBase >= 128) {
        const size_t rowBase = (size_t)mtile * 128;
#pragma unroll
        for (int mi = 0; mi < 4; mi++)
#pragma unroll
            for (int ni = 0; ni < 8; ni++) {
                int j = (nBase - 128) + ni * 8 + qc * 2;
#pragma unroll
                for (int half = 0; half < 2; half++) {
                    int r = mBase + mi * 16 + qr + half * 8;
                    float g0 = sE[r * 130 + j];
                    float g1 = sE[r * 130 + j + 1];
                    float u0 = acc[mi][ni][half * 2];
                    float u1 = acc[mi][ni][half * 2 + 1];
                    float h0 = g0 * (1.0f / (1.0f + __expf(-g0))) * u0;
                    float h1 = g1 * (1.0f / (1.0f + __expf(-g1))) * u1;
                    __half2 hv = __floats2half2_rn(h0, h1);
                    *(__half2*)&g_hbh[(rowBase + r) * In + (size_t)n0 + j] = hv;
                }
            }
    }

    // ---- overlapped w2 fp32 -> fp16 conversion slice -------------------------
    cvt_w2_slice(w2, ctaid, ncta, tid);
}

// =============================================================================
// GEMM2: out[tok] += wt * (h W2^T).  CTA tile M=128 x N=256 out cols, K = In.
// Epilogue atomically accumulates fp32 into out (2 commutative adds/element).
// =============================================================================
__global__ __launch_bounds__(256, 1) void k_gemm2(float* __restrict__ out) {
    extern __shared__ __align__(16) char smraw[];
    const int ntile = blockIdx.x, mtile = blockIdx.y;  // ntile fast (w2 L2-resident)
    if (mtile * 128 >= g_off[En]) return;
    int e = 0;
#pragma unroll
    for (int i = 0; i < En; i++) if (mtile * 128 >= g_off[i + 1]) e = i + 1;
    const int n0 = ntile * 256;
    const int tid = threadIdx.x;

    const uint32_t sb = smem_u32(smraw);
    const uint32_t sbA = sb, sbB = sb + BOFF_B;

    const int r0 = tid >> 4, sg = tid & 15;
    const int strA = In;
    const __half* pA0 = g_hbh + (size_t)(mtile * 128 + r0) * In + sg * 8;
    const __half* pB0 = g_w2h + ((size_t)e * Hn + n0 + r0) * In + sg * 8;
    const uint32_t sA0 = sbA + r0 * ROWP_B + sg * 16;
    const uint32_t sB0 = sbB + r0 * ROWP_B + sg * 16;
#define B_ADDR(q) (pB0 + (size_t)(q) * 16 * In)

    const int w = tid >> 5, lane = tid & 31;
    const int mBase = (w & 1) * 64, nBase = (w >> 1) * 64;
    const int qr = lane >> 2, qc = lane & 3;
    const int loff = ldm_lane_off(lane);

    float acc[4][8][4];
#pragma unroll
    for (int a = 0; a < 4; a++)
#pragma unroll
        for (int b = 0; b < 8; b++)
#pragma unroll
            for (int c = 0; c < 4; c++) acc[a][b][c] = 0.0f;

    GEMM_MAINLOOP(In / 128)  // 22 chunks
#undef B_ADDR

    // ---- epilogue: atomic fp32 accumulate into out ---------------------------
    const size_t rowBase = (size_t)mtile * 128;
#pragma unroll
    for (int mi = 0; mi < 4; mi++) {
#pragma unroll
        for (int half = 0; half < 2; half++) {
            int r = mBase + mi * 16 + qr + half * 8;
            int tok = g_tok[rowBase + r];
            if (tok < 0) continue;
            float wt = g_wt[rowBase + r];
            float* orow = out + (size_t)tok * Hn + n0;
#pragma unroll
            for (int ni = 0; ni < 8; ni++) {
                int c = nBase + ni * 8 + qc * 2;
                atomicAdd(&orow[c], wt * acc[mi][ni][half * 2]);
                atomicAdd(&orow[c + 1], wt * acc[mi][ni][half * 2 + 1]);
            }
        }
    }
}

// ------------------- launcher -------------------------------------------------
extern "C" void kernel_launch(void* const* d_in, const int* in_sizes, int n_in,
                              void* d_out, int out_size) {
    const float* x      = (const float*)d_in[0];
    const float* logits = (const float*)d_in[1];
    const float* w13    = (const float*)d_in[2];
    const float* w2     = (const float*)d_in[3];
    float* out = (float*)d_out;

    cudaFuncSetAttribute(k_gemm1, cudaFuncAttributeMaxDynamicSharedMemorySize, SMEM_BYTES);
    cudaFuncSetAttribute(k_gemm2, cudaFuncAttributeMaxDynamicSharedMemorySize, SMEM_BYTES);

    k_init<<<68, 256>>>();
    k_router<<<Tn / 256, 256>>>(logits);
    k_off<<<1, 32>>>();
    k_scatter<<<2048, 256>>>(w13);                 // scatter + w13 cvt part 1
    k_gather<<<MAXP, 256>>>(x, w13, out);          // gather + w13 cvt part 2 + zero out
    k_gemm1<<<dim3(MAXP / 128, In / 128), 256, SMEM_BYTES>>>(w2);   // (136, 22) + w2 cvt
    k_gemm2<<<dim3(Hn / 256, MAXP / 128), 256, SMEM_BYTES>>>(out);  // (4, 136) + atomic out
}

// round 13
// speedup vs baseline: 1.0165x; 1.0165x over previous
#include <cuda_runtime.h>
#include <cuda_fp16.h>
#include <cstdint>

#define Tn 8192
#define Hn 1024
#define In 2816
#define En 8
#define MAXP 17408  // 16384 pairs + per-expert 128-alignment padding

// ------------------- device scratch (no allocations allowed) -----------------
__device__ int    g_cnt[En];
__device__ int    g_cur[En];
__device__ int    g_off[En + 1];
__device__ int    g_eid[Tn * 2];
__device__ float  g_ew[Tn * 2];
__device__ int    g_tok[MAXP];
__device__ float  g_wt[MAXP];
__device__ __half g_xh[(size_t)MAXP * Hn];           // gathered x rows, fp16
__device__ __half g_hbh[(size_t)MAXP * In];          // silu(gate)*up, fp16
__device__ __half g_w13h[(size_t)En * 2 * In * Hn];  // fp16 w13 (92MB)
__device__ __half g_w2h[(size_t)En * Hn * In];       // fp16 w2  (46MB)

// ------------------- helpers -------------------------------------------------
__device__ __forceinline__ uint32_t smem_u32(const void* p) {
    uint32_t a;
    asm("{ .reg .u64 t; cvta.to.shared.u64 t, %1; cvt.u32.u64 %0, t; }" : "=r"(a) : "l"(p));
    return a;
}
__device__ __forceinline__ void cp16(uint32_t saddr, const void* gsrc) {
    asm volatile("cp.async.cg.shared.global [%0], [%1], 16;\n" :: "r"(saddr), "l"(gsrc));
}
// fp16 m16n8k16 mma, fp32 accumulate
__device__ __forceinline__ void mma16(float* c, const uint32_t* a, const uint32_t* b) {
    asm volatile(
        "mma.sync.aligned.m16n8k16.row.col.f32.f16.f16.f32 "
        "{%0,%1,%2,%3}, {%4,%5,%6,%7}, {%8,%9}, {%0,%1,%2,%3};\n"
        : "+f"(c[0]), "+f"(c[1]), "+f"(c[2]), "+f"(c[3])
        : "r"(a[0]), "r"(a[1]), "r"(a[2]), "r"(a[3]), "r"(b[0]), "r"(b[1]));
}
__device__ __forceinline__ void ldm4(uint32_t* r, uint32_t addr) {
    asm volatile("ldmatrix.sync.aligned.m8n8.x4.shared.b16 {%0,%1,%2,%3}, [%4];"
                 : "=r"(r[0]), "=r"(r[1]), "=r"(r[2]), "=r"(r[3]) : "r"(addr));
}
__device__ __forceinline__ uint32_t h2u(__half2 h) { return *(uint32_t*)&h; }

// smem layout: K-chunk = 128 halves (256 B/row), pitch 136 halves (272 B/row).
// Stage: A 128x272B = 34,816 B; B 256x272B = 69,632 B -> 104,448 B.
static constexpr int ROWP_B = 272;              // row pitch bytes
static constexpr int STG_B  = 104448;           // bytes per stage
static constexpr int BOFF_B = 34816;            // B offset within stage
static constexpr int SMEM_BYTES = STG_B * 2;    // 208,896 B (2 stages)

// ------------------- kernel: weights->fp16 + state init + zero out -----------
__global__ void k_cvtw(const float* __restrict__ w13, const float* __restrict__ w2,
                       float* __restrict__ out) {
    long gid = (long)blockIdx.x * blockDim.x + threadIdx.x;
    if (gid < En) { g_cnt[gid] = 0; g_cur[gid] = 0; }
    const long stride = (long)gridDim.x * blockDim.x;
    for (long s = gid; s < MAXP; s += stride) {
        g_tok[s] = -1;
        g_wt[s] = 0.0f;
    }
    // zero the output accumulator (GEMM2 atomically adds into it)
    for (long i = gid; i < (long)Tn * Hn / 4; i += stride)
        ((float4*)out)[i] = make_float4(0.f, 0.f, 0.f, 0.f);
    const long N1 = (long)En * 2 * In * Hn / 4;
    const long N2 = (long)En * Hn * In / 4;
    for (long i = gid; i < N1 + N2; i += stride) {
        float4 v = (i < N1) ? ((const float4*)w13)[i] : ((const float4*)w2)[i - N1];
        uint2 pk;
        pk.x = h2u(__floats2half2_rn(v.x, v.y));
        pk.y = h2u(__floats2half2_rn(v.z, v.w));
        if (i < N1) ((uint2*)g_w13h)[i] = pk;
        else        ((uint2*)g_w2h)[i - N1] = pk;
    }
}

// ------------------- kernel: router ------------------------------------------
__global__ void k_router(const float* __restrict__ logits) {
    int t = blockIdx.x * blockDim.x + threadIdx.x;
    if (t >= Tn) return;
    float v[En];
#pragma unroll
    for (int e = 0; e < En; e++) v[e] = logits[t * En + e];
    int b0 = 0; float m0 = v[0];
#pragma unroll
    for (int e = 1; e < En; e++) if (v[e] > m0) { m0 = v[e]; b0 = e; }
    int b1 = -1; float m1 = -3.0e38f;
#pragma unroll
    for (int e = 0; e < En; e++) if (e != b0 && v[e] > m1) { m1 = v[e]; b1 = e; }
    float e1 = expf(m1 - m0);
    float inv = 1.0f / (1.0f + e1);
    g_eid[2 * t] = b0;     g_ew[2 * t] = inv;
    g_eid[2 * t + 1] = b1; g_ew[2 * t + 1] = e1 * inv;
    atomicAdd(&g_cnt[b0], 1);
    atomicAdd(&g_cnt[b1], 1);
}

// ------------------- kernel: 128-aligned offsets ------------------------------
__global__ void k_off() {
    if (threadIdx.x == 0 && blockIdx.x == 0) {
        int o = 0;
        g_off[0] = 0;
        for (int e = 0; e < En; e++) {
            o += (g_cnt[e] + 127) & ~127;
            g_off[e + 1] = o;
        }
    }
}

// ------------------- kernel: scatter ------------------------------------------
__global__ void k_scatter() {
    int t = blockIdx.x * blockDim.x + threadIdx.x;
    if (t >= Tn) return;
#pragma unroll
    for (int k = 0; k < 2; k++) {
        int e = g_eid[2 * t + k];
        int pos = atomicAdd(&g_cur[e], 1);
        int s = g_off[e] + pos;
        g_tok[s] = t;
        g_wt[s] = g_ew[2 * t + k];
    }
}

// ------------------- kernel: gather x rows -> fp16 ----------------------------
__global__ void k_gather(const float* __restrict__ x) {
    int s = blockIdx.x;
    int tok = g_tok[s];
    uint2 pk = { 0u, 0u };
    if (tok >= 0) {
        float4 v = *(const float4*)&x[(size_t)tok * Hn + threadIdx.x * 4];
        pk.x = h2u(__floats2half2_rn(v.x, v.y));
        pk.y = h2u(__floats2half2_rn(v.z, v.w));
    }
    *(uint2*)&g_xh[(size_t)s * Hn + threadIdx.x * 4] = pk;
}

// =============================================================================
// GEMM mainloop: CTA tile M=128 x 256 B-rows, fp16 m16n8k16.
// K-chunk = 128 halves (256 B/row), pitch-136 smem rows, 2-stage cp.async
// pipeline (lookahead 1), ldmatrix fragment loads, 8 warps of 64x64.
// =============================================================================

__device__ __forceinline__ int ldm_lane_off(int lane) {
    int lr = lane & 7, grp = lane >> 3;
    int rowoff = lr + (grp & 1) * 8;
    int coloff = (grp >> 1) * 8;
    return rowoff * ROWP_B + coloff * 2;
}

#define LOAD_CHUNK(c, st) do {                                                     \
    const uint32_t _sA = sA0 + (st) * STG_B;                                       \
    const uint32_t _sB = sB0 + (st) * STG_B;                                       \
    _Pragma("unroll")                                                              \
    for (int q = 0; q < 8; q++)                                                    \
        cp16(_sA + q * 16 * ROWP_B, pA0 + (size_t)q * 16 * strA + (c) * 128);      \
    _Pragma("unroll")                                                              \
    for (int q = 0; q < 16; q++)                                                   \
        cp16(_sB + q * 16 * ROWP_B, B_ADDR(q) + (c) * 128);                        \
    asm volatile("cp.async.commit_group;" ::: "memory");                           \
} while (0)

#define GEMM_MAINLOOP(NC)                                                          \
    LOAD_CHUNK(0, 0);                                                              \
    LOAD_CHUNK(1, 1);                                                              \
    for (int i = 0; i < (NC); i++) {                                               \
        const int st = i & 1;                                                      \
        asm volatile("cp.async.wait_group 1;" ::: "memory");                       \
        __syncthreads();                                                           \
        const uint32_t aS = sbA + st * STG_B;                                      \
        const uint32_t bS = sbB + st * STG_B;                                      \
        _Pragma("unroll")                                                          \
        for (int ks = 0; ks < 8; ks++) {                                           \
            const int k0b = ks * 32;                                               \
            uint32_t af[4][4], bf[8][2];                                           \
            _Pragma("unroll")                                                      \
            for (int mi = 0; mi < 4; mi++)                                         \
                ldm4(af[mi], aS + (mBase + mi * 16) * ROWP_B + k0b + loff);        \
            _Pragma("unroll")                                                      \
            for (int nj = 0; nj < 4; nj++) {                                       \
                uint32_t t4[4];                                                    \
                ldm4(t4, bS + (nBase + nj * 16) * ROWP_B + k0b + loff);            \
                bf[nj * 2][0] = t4[0]; bf[nj * 2 + 1][0] = t4[1];                  \
                bf[nj * 2][1] = t4[2]; bf[nj * 2 + 1][1] = t4[3];                  \
            }                                                                      \
            _Pragma("unroll")                                                      \
            for (int mi = 0; mi < 4; mi++)                                         \
                _Pragma("unroll")                                                  \
                for (int ni = 0; ni < 8; ni++) mma16(acc[mi][ni], af[mi], bf[ni]); \
        }                                                                          \
        __syncthreads();                                                           \
        if (i + 2 < (NC)) LOAD_CHUNK(i + 2, st);                                   \
        else asm volatile("cp.async.commit_group;" ::: "memory");                  \
    }

// =============================================================================
// GEMM1: h = silu(x W1^T) * (x W3^T). B-rows 0..127 = gate, 128..255 = up.
// =============================================================================
__global__ __launch_bounds__(256, 1) void k_gemm1() {
    extern __shared__ __align__(16) char smraw[];
    const int mtile = blockIdx.x, ntile = blockIdx.y;  // mtile fast (A L2-reuse)
    if (mtile * 128 >= g_off[En]) return;
    int e = 0;
#pragma unroll
    for (int i = 0; i < En; i++) if (mtile * 128 >= g_off[i + 1]) e = i + 1;
    const int n0 = ntile * 128;
    const int tid = threadIdx.x;

    const uint32_t sb = smem_u32(smraw);
    const uint32_t sbA = sb, sbB = sb + BOFF_B;

    // loader bases: r0 = tid>>4 (0..15), sg = tid&15
    const int r0 = tid >> 4, sg = tid & 15;
    const int strA = Hn;  // halves per A row
    const __half* pA0 = g_xh + (size_t)(mtile * 128 + r0) * Hn + sg * 8;
    const __half* pBg = g_w13h + ((size_t)e * 2 * In + n0 + r0) * Hn + sg * 8;
    const __half* pBu = g_w13h + ((size_t)e * 2 * In + In + n0 + r0) * Hn + sg * 8;
    const uint32_t sA0 = sbA + r0 * ROWP_B + sg * 16;
    const uint32_t sB0 = sbB + r0 * ROWP_B + sg * 16;
#define B_ADDR(q) ((q) < 8 ? (pBg + (size_t)(q) * 16 * Hn) : (pBu + (size_t)((q) - 8) * 16 * Hn))

    const int w = tid >> 5, lane = tid & 31;
    const int mBase = (w & 1) * 64, nBase = (w >> 1) * 64;
    const int qr = lane >> 2, qc = lane & 3;
    const int loff = ldm_lane_off(lane);

    float acc[4][8][4];
#pragma unroll
    for (int a = 0; a < 4; a++)
#pragma unroll
        for (int b = 0; b < 8; b++)
#pragma unroll
            for (int c = 0; c < 4; c++) acc[a][b][c] = 0.0f;

    GEMM_MAINLOOP(Hn / 128)  // 8 chunks
#undef B_ADDR

    // ---- epilogue: gate warps stage to smem; up warps compute silu(g)*u ------
    float* sE = (float*)smraw;  // 128 x pitch-130 floats = 66,560 B (fits)
    if (nBase < 128) {
#pragma unroll
        for (int mi = 0; mi < 4; mi++)
#pragma unroll
            for (int ni = 0; ni < 8; ni++) {
                int r = mBase + mi * 16 + qr;
                int c = nBase + ni * 8 + qc * 2;
                sE[r * 130 + c] = acc[mi][ni][0];
                sE[r * 130 + c + 1] = acc[mi][ni][1];
                sE[(r + 8) * 130 + c] = acc[mi][ni][2];
                sE[(r + 8) * 130 + c + 1] = acc[mi][ni][3];
            }
    }
    __syncthreads();
    if (nBase >= 128) {
        const size_t rowBase = (size_t)mtile * 128;
#pragma unroll
        for (int mi = 0; mi < 4; mi++)
#pragma unroll
            for (int ni = 0; ni < 8; ni++) {
                int j = (nBase - 128) + ni * 8 + qc * 2;
#pragma unroll
                for (int half = 0; half < 2; half++) {
                    int r = mBase + mi * 16 + qr + half * 8;
                    float g0 = sE[r * 130 + j];
                    float g1 = sE[r * 130 + j + 1];
                    float u0 = acc[mi][ni][half * 2];
                    float u1 = acc[mi][ni][half * 2 + 1];
                    float h0 = g0 * (1.0f / (1.0f + __expf(-g0))) * u0;
                    float h1 = g1 * (1.0f / (1.0f + __expf(-g1))) * u1;
                    __half2 hv = __floats2half2_rn(h0, h1);
                    *(__half2*)&g_hbh[(rowBase + r) * In + (size_t)n0 + j] = hv;
                }
            }
    }
}

// =============================================================================
// GEMM2: out[tok] += wt * (h W2^T).  CTA tile M=128 x N=256 out cols, K = In.
// Epilogue atomically accumulates fp32 into out (2 commutative adds/element,
// deterministic values).
// =============================================================================
__global__ __launch_bounds__(256, 1) void k_gemm2(float* __restrict__ out) {
    extern __shared__ __align__(16) char smraw[];
    const int ntile = blockIdx.x, mtile = blockIdx.y;  // ntile fast (w2 L2-resident)
    if (mtile * 128 >= g_off[En]) return;
    int e = 0;
#pragma unroll
    for (int i = 0; i < En; i++) if (mtile * 128 >= g_off[i + 1]) e = i + 1;
    const int n0 = ntile * 256;
    const int tid = threadIdx.x;

    const uint32_t sb = smem_u32(smraw);
    const uint32_t sbA = sb, sbB = sb + BOFF_B;

    const int r0 = tid >> 4, sg = tid & 15;
    const int strA = In;
    const __half* pA0 = g_hbh + (size_t)(mtile * 128 + r0) * In + sg * 8;
    const __half* pB0 = g_w2h + ((size_t)e * Hn + n0 + r0) * In + sg * 8;
    const uint32_t sA0 = sbA + r0 * ROWP_B + sg * 16;
    const uint32_t sB0 = sbB + r0 * ROWP_B + sg * 16;
#define B_ADDR(q) (pB0 + (size_t)(q) * 16 * In)

    const int w = tid >> 5, lane = tid & 31;
    const int mBase = (w & 1) * 64, nBase = (w >> 1) * 64;
    const int qr = lane >> 2, qc = lane & 3;
    const int loff = ldm_lane_off(lane);

    float acc[4][8][4];
#pragma unroll
    for (int a = 0; a < 4; a++)
#pragma unroll
        for (int b = 0; b < 8; b++)
#pragma unroll
            for (int c = 0; c < 4; c++) acc[a][b][c] = 0.0f;

    GEMM_MAINLOOP(In / 128)  // 22 chunks
#undef B_ADDR

    // ---- epilogue: atomic fp32 accumulate into out ---------------------------
    const size_t rowBase = (size_t)mtile * 128;
#pragma unroll
    for (int mi = 0; mi < 4; mi++) {
#pragma unroll
        for (int half = 0; half < 2; half++) {
            int r = mBase + mi * 16 + qr + half * 8;
            int tok = g_tok[rowBase + r];
            if (tok < 0) continue;
            float wt = g_wt[rowBase + r];
            float* orow = out + (size_t)tok * Hn + n0;
#pragma unroll
            for (int ni = 0; ni < 8; ni++) {
                int c = nBase + ni * 8 + qc * 2;
                atomicAdd(&orow[c], wt * acc[mi][ni][half * 2]);
                atomicAdd(&orow[c + 1], wt * acc[mi][ni][half * 2 + 1]);
            }
        }
    }
}

// ------------------- launcher -------------------------------------------------
extern "C" void kernel_launch(void* const* d_in, const int* in_sizes, int n_in,
                              void* d_out, int out_size) {
    const float* x      = (const float*)d_in[0];
    const float* logits = (const float*)d_in[1];
    const float* w13    = (const float*)d_in[2];
    const float* w2     = (const float*)d_in[3];
    float* out = (float*)d_out;

    cudaFuncSetAttribute(k_gemm1, cudaFuncAttributeMaxDynamicSharedMemorySize, SMEM_BYTES);
    cudaFuncSetAttribute(k_gemm2, cudaFuncAttributeMaxDynamicSharedMemorySize, SMEM_BYTES);

    k_cvtw<<<2048, 256>>>(w13, w2, out);  // weights->fp16 + init + zero out
    k_router<<<Tn / 256, 256>>>(logits);
    k_off<<<1, 32>>>();
    k_scatter<<<Tn / 256, 256>>>();
    k_gather<<<MAXP, 256>>>(x);
    k_gemm1<<<dim3(MAXP / 128, In / 128), 256, SMEM_BYTES>>>();     // (136, 22)
    k_gemm2<<<dim3(Hn / 256, MAXP / 128), 256, SMEM_BYTES>>>(out);  // (4, 136)
}